// round 16
// baseline (speedup 1.0000x reference)
#include <cuda_runtime.h>

#define HID 64
typedef unsigned long long u64;

__device__ __forceinline__ u64 pk2(float lo, float hi) {
    u64 r; asm("mov.b64 %0, {%1,%2};" : "=l"(r) : "f"(lo), "f"(hi)); return r;
}
__device__ __forceinline__ void upk2(u64 v, float& lo, float& hi) {
    asm("mov.b64 {%0,%1}, %2;" : "=f"(lo), "=f"(hi) : "l"(v));
}
__device__ __forceinline__ u64 ffma2(u64 a, u64 b, u64 c) {
    u64 d; asm("fma.rn.f32x2 %0, %1, %2, %3;" : "=l"(d) : "l"(a), "l"(b), "l"(c)); return d;
}
__device__ __forceinline__ u64 fmul2(u64 a, u64 b) {
    u64 d; asm("mul.rn.f32x2 %0, %1, %2;" : "=l"(d) : "l"(a), "l"(b)); return d;
}

__global__ void zero_kernel(float* __restrict__ out, int n) {
    int i = blockIdx.x * blockDim.x + threadIdx.x;
    if (i < n) out[i] = 0.0f;
}

// h-PAIR packed weights (16-u64 / 128B block per h2), attr folded into
// layer 2, 3 packed accumulators per edge.
// This round: layer-1 goes FFMA2 too — d stored DUPLICATED (d,d) so the
// h-pair W1 weights (loaded as ulonglong2, .x/.y are ready u64 operands)
// multiply directly: 3 FFMA2 instead of 6 scalar FFMA per edge per h2.
// fma slots/edge/h2: 18 -> 15. EPT3B=5 keeps regs under the 4-block cap.
template<int DIN, int EPT>
__device__ __forceinline__ void run_family(
    const float* __restrict__ x,
    const int*   __restrict__ edges,
    const float* __restrict__ attr,
    const float* __restrict__ W1, const float* __restrict__ b1,
    const float* __restrict__ W2, const float* __restrict__ b2,
    float* __restrict__ out, int E, int blk, int nblk, u64* smem)
{
    u64*   sWB = smem;                      // [16 * 32]
    float* sB2 = (float*)(sWB + 16 * 32);   // [9]

    for (int idx = threadIdx.x; idx < 16 * 32; idx += blockDim.x) {
        int h2 = idx >> 4, s = idx & 15;
        int h0 = 2 * h2, h1 = 2 * h2 + 1;
        float lo = 0.0f, hi = 0.0f;
        if (s < DIN)           { lo = W1[s * HID + h0]; hi = W1[s * HID + h1]; }
        else if (s == DIN)     { lo = b1[h0];           hi = b1[h1]; }
        else if (s <= DIN + 9) { int m = s - DIN - 1; lo = W2[h0 * 9 + m]; hi = W2[h1 * 9 + m]; }
        sWB[idx] = pk2(lo, hi);
    }
    if (threadIdx.x < 9) sB2[threadIdx.x] = b2[threadIdx.x];
    __syncthreads();

    const int tid    = blk * (int)blockDim.x + (int)threadIdx.x;
    const int stride = nblk * (int)blockDim.x;

    u64   dd[EPT][DIN];    // (d,d) duplicated MLP inputs
    u64   atd[EPT][3];     // (at_m, at_m) duplicated attrs
    u64   acc[EPT][3];     // packed y accumulators (even-h lane0, odd-h lane1)
    int   tgt[EPT];

    #pragma unroll
    for (int k = 0; k < EPT; k++) {
        int e = tid + k * stride;
        int ee = (e < E) ? e : 0;
        float dv[DIN];
        int i;
        if (DIN == 3) {
            int j = edges[ee];
            i = edges[E + ee];
            dv[0] = x[3*j+0] - x[3*i+0];
            dv[1] = x[3*j+1] - x[3*i+1];
            dv[2] = x[3*j+2] - x[3*i+2];
        } else {
            int j  = edges[ee];
            int kk = edges[E + ee];
            i = edges[2*E + ee];
            float xk0 = x[3*kk+0], xk1 = x[3*kk+1], xk2 = x[3*kk+2];
            dv[0] = xk0 - x[3*j+0];
            dv[1] = xk1 - x[3*j+1];
            dv[2] = xk2 - x[3*j+2];
            dv[3] = x[3*i+0] - xk0;
            dv[4] = x[3*i+1] - xk1;
            dv[5] = x[3*i+2] - xk2;
        }
        tgt[k] = i;
        #pragma unroll
        for (int q = 0; q < DIN; q++) dd[k][q] = pk2(dv[q], dv[q]);
        float a0 = attr[3*ee+0], a1 = attr[3*ee+1], a2v = attr[3*ee+2];
        atd[k][0] = pk2(a0, a0);
        atd[k][1] = pk2(a1, a1);
        atd[k][2] = pk2(a2v, a2v);
        // seed with b2 . attr (even-h lane)
        #pragma unroll
        for (int i2 = 0; i2 < 3; i2++) {
            float s0 = fmaf(sB2[3*i2+0], a0,
                       fmaf(sB2[3*i2+1], a1, sB2[3*i2+2] * a2v));
            acc[k][i2] = pk2(s0, 0.0f);
        }
    }

    // Mainloop: 32 h-pair iterations.
    #pragma unroll 4
    for (int h2 = 0; h2 < 32; h2++) {
        const u64*        wp = sWB + h2 * 16;
        const ulonglong2* wv = (const ulonglong2*)wp;
        u64 hv[EPT];

        if (DIN == 3) {
            ulonglong2 qa = wv[0];   // (w1_0 pair, w1_1 pair)
            ulonglong2 qb = wv[1];   // (w1_2 pair, b1 pair)
            #pragma unroll
            for (int k = 0; k < EPT; k++) {
                u64 t = ffma2(dd[k][0], qa.x, qb.y);
                t = ffma2(dd[k][1], qa.y, t);
                t = ffma2(dd[k][2], qb.x, t);
                float lo, hi; upk2(t, lo, hi);
                hv[k] = pk2(fmaxf(lo, 0.0f), fmaxf(hi, 0.0f));
            }
        } else {
            ulonglong2 qa = wv[0];   // (w1_0, w1_1)
            ulonglong2 qb = wv[1];   // (w1_2, w1_3)
            ulonglong2 qc = wv[2];   // (w1_4, w1_5)
            ulonglong2 qd = wv[3];   // (b1, w2_0)
            #pragma unroll
            for (int k = 0; k < EPT; k++) {
                u64 t = ffma2(dd[k][0], qa.x, qd.x);
                t = ffma2(dd[k][1], qa.y, t);
                t = ffma2(dd[k][2], qb.x, t);
                t = ffma2(dd[k][3], qb.y, t);
                t = ffma2(dd[k][4], qc.x, t);
                t = ffma2(dd[k][5], qc.y, t);
                float lo, hi; upk2(t, lo, hi);
                hv[k] = pk2(fmaxf(lo, 0.0f), fmaxf(hi, 0.0f));
            }
        }

        // Layer 2, i-outer / k-inner: only 3 W2 pairs live at a time,
        // loaded directly as u64 (LDS.64, no packing movs).
        #pragma unroll
        for (int i = 0; i < 3; i++) {
            u64 w0 = wp[DIN + 1 + 3*i + 0];
            u64 w1 = wp[DIN + 1 + 3*i + 1];
            u64 w2 = wp[DIN + 1 + 3*i + 2];
            #pragma unroll
            for (int k = 0; k < EPT; k++) {
                u64 t = fmul2(w2, atd[k][2]);
                t = ffma2(w1, atd[k][1], t);
                t = ffma2(w0, atd[k][0], t);
                acc[k][i] = ffma2(hv[k], t, acc[k][i]);
            }
        }
    }

    // Epilogue: y_i = lane0 + lane1, scatter-add (valid recomputed).
    #pragma unroll
    for (int k = 0; k < EPT; k++) {
        if (tid + k * stride < E) {
            #pragma unroll
            for (int i = 0; i < 3; i++) {
                float lo, hi; upk2(acc[k][i], lo, hi);
                atomicAdd(&out[3*tgt[k] + i], lo + hi);
            }
        }
    }
}

#define EPT3B 5   // DIN=3 families
#define EPT6B 3   // DIN=6 family

__global__ __launch_bounds__(128, 4)
void fused_hignn_kernel(
    const float* __restrict__ x,
    const int* __restrict__ e2, const float* __restrict__ a2,
    const float* __restrict__ W1_2b, const float* __restrict__ b1_2b,
    const float* __restrict__ W2_2b, const float* __restrict__ b2_2b,
    const int* __restrict__ e3, const float* __restrict__ a3,
    const float* __restrict__ W1_3b, const float* __restrict__ b1_3b,
    const float* __restrict__ W2_3b, const float* __restrict__ b2_3b,
    const int* __restrict__ es, const float* __restrict__ as,
    const float* __restrict__ W1_s, const float* __restrict__ b1_s,
    const float* __restrict__ W2_s, const float* __restrict__ b2_s,
    float* __restrict__ out,
    int E2, int E3, int ES, int B2, int B3, int BS)
{
    __shared__ __align__(16) u64 smem[16 * 32 + 8];
    int b = blockIdx.x;
    if (b < B2) {
        run_family<3, EPT3B>(x, e2, a2, W1_2b, b1_2b, W2_2b, b2_2b, out, E2, b, B2, smem);
    } else if (b < B2 + B3) {
        run_family<6, EPT6B>(x, e3, a3, W1_3b, b1_3b, W2_3b, b2_3b, out, E3, b - B2, B3, smem);
    } else {
        run_family<3, EPT3B>(x, es, as, W1_s, b1_s, W2_s, b2_s, out, ES, b - B2 - B3, BS, smem);
    }
}

extern "C" void kernel_launch(void* const* d_in, const int* in_sizes, int n_in,
                              void* d_out, int out_size)
{
    const float* x   = (const float*)d_in[0];
    const int*   e2  = (const int*)  d_in[1];
    const int*   e3  = (const int*)  d_in[2];
    const int*   es  = (const int*)  d_in[3];
    const float* a2  = (const float*)d_in[5];
    const float* a3  = (const float*)d_in[6];
    const float* as  = (const float*)d_in[7];
    const float* W1_2b = (const float*)d_in[9];
    const float* b1_2b = (const float*)d_in[10];
    const float* W2_2b = (const float*)d_in[11];
    const float* b2_2b = (const float*)d_in[12];
    const float* W1_3b = (const float*)d_in[13];
    const float* b1_3b = (const float*)d_in[14];
    const float* W2_3b = (const float*)d_in[15];
    const float* b2_3b = (const float*)d_in[16];
    const float* W1_s  = (const float*)d_in[17];
    const float* b1_s  = (const float*)d_in[18];
    const float* W2_s  = (const float*)d_in[19];
    const float* b2_s  = (const float*)d_in[20];

    const int E2 = in_sizes[1] / 2;
    const int E3 = in_sizes[2] / 3;
    const int ES = in_sizes[3] / 2;

    float* out = (float*)d_out;

    zero_kernel<<<(out_size + 255) / 256, 256>>>(out, out_size);

    constexpr int BLK = 128;
    const int B2 = (E2 + EPT3B * BLK - 1) / (EPT3B * BLK);
    const int B3 = (E3 + EPT6B * BLK - 1) / (EPT6B * BLK);
    const int BS = (ES + EPT3B * BLK - 1) / (EPT3B * BLK);

    fused_hignn_kernel<<<B2 + B3 + BS, BLK>>>(
        x,
        e2, a2, W1_2b, b1_2b, W2_2b, b2_2b,
        e3, a3, W1_3b, b1_3b, W2_3b, b2_3b,
        es, as, W1_s, b1_s, W2_s, b2_s,
        out, E2, E3, ES, B2, B3, BS);
}